// round 1
// baseline (speedup 1.0000x reference)
#include <cuda_runtime.h>
#include <math.h>

#define NB 4
#define NH 16
#define NT 2048
#define NE 1024
#define ND 64
#define NM (NB*NT)   // 8192 rows

// Scratch (alloc-free rule: __device__ globals)
__device__ float g_q[NB*NH*NT*ND];    // [B,H,T,D]
__device__ float g_k[NB*NH*NT*ND];
__device__ float g_v[NB*NH*NT*ND];
__device__ float g_att[NB*NT*NE];     // [B,T,E]

// ---------------------------------------------------------------------------
// GEMM: C = X @ W^T + bias.  X:[M,K] row-major, W:[N,K] row-major.
// 128x128 block tile, BK=8, 256 threads, 8x8 register micro-tile (strided 16).
// MODE 0: plain C[m*N+n]   MODE 1: scatter to [B,H,T,D] (n = h*64+d, m = b*T+t)
// ---------------------------------------------------------------------------
template<int MODE>
__global__ __launch_bounds__(256) void gemm_xwt_kernel(
    const float* __restrict__ X, const float* __restrict__ W,
    const float* __restrict__ bias, float* __restrict__ C,
    int M, int N, int K)
{
    __shared__ float Xs[8*132];   // [k][m], pad 132 -> conflict-free ld/st
    __shared__ float Ws[8*132];   // [k][n]
    const int tid = threadIdx.x;
    const int tx = tid & 15, ty = tid >> 4;
    const int n0 = blockIdx.x * 128;
    const int m0 = blockIdx.y * 128;

    float acc[8][8];
    #pragma unroll
    for (int i = 0; i < 8; i++)
        #pragma unroll
        for (int j = 0; j < 8; j++) acc[i][j] = 0.f;

    for (int kt = 0; kt < K; kt += 8) {
        #pragma unroll
        for (int r = 0; r < 4; r++) {
            int idx = tid + r*256;          // 1024 elems per tile
            int row = idx >> 3, kc = idx & 7;
            Xs[kc*132 + row] = X[(m0+row)*K + kt + kc];
            Ws[kc*132 + row] = W[(n0+row)*K + kt + kc];
        }
        __syncthreads();
        #pragma unroll
        for (int k = 0; k < 8; k++) {
            float a[8], bb[8];
            #pragma unroll
            for (int i = 0; i < 8; i++) a[i]  = Xs[k*132 + ty + 16*i];
            #pragma unroll
            for (int j = 0; j < 8; j++) bb[j] = Ws[k*132 + tx + 16*j];
            #pragma unroll
            for (int i = 0; i < 8; i++)
                #pragma unroll
                for (int j = 0; j < 8; j++)
                    acc[i][j] += a[i]*bb[j];
        }
        __syncthreads();
    }

    #pragma unroll
    for (int i = 0; i < 8; i++) {
        int m = m0 + ty + 16*i;
        #pragma unroll
        for (int j = 0; j < 8; j++) {
            int n = n0 + tx + 16*j;
            float v = acc[i][j] + bias[n];
            if (MODE == 0) {
                C[m*N + n] = v;
            } else {
                int b = m >> 11;      // m / 2048
                int t = m & 2047;
                int h = n >> 6;       // n / 64
                int d = n & 63;
                C[((((b*NH + h)*NT) + t) << 6) + d] = v;
            }
        }
    }
}

// ---------------------------------------------------------------------------
// Fused causal flash attention. One block = (q-tile 64 rows, head, batch).
// 256 threads; 4x4 micro-tile strided 16 (conflict-free smem reads).
// Streaming softmax (m, l per row). Skips k-tiles above the diagonal.
// ---------------------------------------------------------------------------
__global__ __launch_bounds__(256) void attn_kernel()
{
    extern __shared__ float sm[];
    float* Qs   = sm;                 // 64 x 65
    float* Ks   = Qs + 64*65;         // 64 x 65
    float* Vs   = Ks + 64*65;         // 64 x 65
    float* Ps   = Vs + 64*65;         // 64 x 65
    float* mrow = Ps + 64*65;         // 64
    float* lrow = mrow + 64;          // 64
    float* crow = lrow + 64;          // 64

    const int qt  = blockIdx.x;
    const int h   = blockIdx.y;
    const int b   = blockIdx.z;
    const int tid = threadIdx.x;
    const int tx  = tid & 15, ty = tid >> 4;

    const float* Qg = g_q + ((b*NH + h)*NT + qt*64) * ND;
    const float* Kg = g_k + ((b*NH + h)*NT) * ND;
    const float* Vg = g_v + ((b*NH + h)*NT) * ND;

    for (int idx = tid; idx < 64*64; idx += 256) {
        int r = idx >> 6, d = idx & 63;
        Qs[r*65 + d] = Qg[idx];
    }
    if (tid < 64) { mrow[tid] = -INFINITY; lrow[tid] = 0.f; }

    float oacc[4][4];
    #pragma unroll
    for (int i = 0; i < 4; i++)
        #pragma unroll
        for (int j = 0; j < 4; j++) oacc[i][j] = 0.f;

    const float scale = 0.125f;  // 1/sqrt(64)

    for (int kt = 0; kt <= qt; kt++) {
        __syncthreads();   // protect Ks/Vs/Ps from previous iteration readers
        const float* Kt = Kg + kt*64*ND;
        const float* Vt = Vg + kt*64*ND;
        for (int idx = tid; idx < 4096; idx += 256) {
            int r = idx >> 6, d = idx & 63;
            Ks[r*65 + d] = Kt[idx];
            Vs[r*65 + d] = Vt[idx];
        }
        __syncthreads();

        // S = Q @ K^T  (64x64x64)
        float acc[4][4];
        #pragma unroll
        for (int i = 0; i < 4; i++)
            #pragma unroll
            for (int j = 0; j < 4; j++) acc[i][j] = 0.f;

        #pragma unroll 8
        for (int d = 0; d < 64; d++) {
            float qv[4], kv[4];
            #pragma unroll
            for (int i = 0; i < 4; i++) qv[i] = Qs[(ty + 16*i)*65 + d];
            #pragma unroll
            for (int j = 0; j < 4; j++) kv[j] = Ks[(tx + 16*j)*65 + d];
            #pragma unroll
            for (int i = 0; i < 4; i++)
                #pragma unroll
                for (int j = 0; j < 4; j++)
                    acc[i][j] += qv[i]*kv[j];
        }

        const bool diag = (kt == qt);
        #pragma unroll
        for (int i = 0; i < 4; i++) {
            int r = ty + 16*i;
            #pragma unroll
            for (int j = 0; j < 4; j++) {
                int c = tx + 16*j;
                float s = acc[i][j] * scale;
                if (diag && c > r) s = -INFINITY;
                Ps[r*65 + c] = s;
            }
        }
        __syncthreads();

        // streaming softmax: one thread per row
        if (tid < 64) {
            const int r = tid;
            float mold = mrow[r];
            float mx = mold;
            #pragma unroll 8
            for (int c = 0; c < 64; c++) mx = fmaxf(mx, Ps[r*65 + c]);
            float corr = __expf(mold - mx);   // 0 on first tile (mold=-inf)
            float sum = 0.f;
            #pragma unroll 8
            for (int c = 0; c < 64; c++) {
                float p = __expf(Ps[r*65 + c] - mx);
                Ps[r*65 + c] = p;
                sum += p;
            }
            lrow[r] = lrow[r]*corr + sum;
            mrow[r] = mx;
            crow[r] = corr;
        }
        __syncthreads();

        // O = O*corr + P @ V
        float cr[4];
        #pragma unroll
        for (int i = 0; i < 4; i++) cr[i] = crow[ty + 16*i];
        #pragma unroll
        for (int i = 0; i < 4; i++)
            #pragma unroll
            for (int j = 0; j < 4; j++) oacc[i][j] *= cr[i];

        #pragma unroll 8
        for (int kk = 0; kk < 64; kk++) {
            float pv[4], vv[4];
            #pragma unroll
            for (int i = 0; i < 4; i++) pv[i] = Ps[(ty + 16*i)*65 + kk];
            #pragma unroll
            for (int j = 0; j < 4; j++) vv[j] = Vs[kk*65 + tx + 16*j];
            #pragma unroll
            for (int i = 0; i < 4; i++)
                #pragma unroll
                for (int j = 0; j < 4; j++)
                    oacc[i][j] += pv[i]*vv[j];
        }
    }

    // finalize + write [B,T,E]
    float li[4];
    #pragma unroll
    for (int i = 0; i < 4; i++) li[i] = 1.f / lrow[ty + 16*i];
    #pragma unroll
    for (int i = 0; i < 4; i++) {
        int t = qt*64 + ty + 16*i;
        #pragma unroll
        for (int j = 0; j < 4; j++) {
            int c = tx + 16*j;
            g_att[(b*NT + t)*NE + h*ND + c] = oacc[i][j] * li[i];
        }
    }
}

// ---------------------------------------------------------------------------
extern "C" void kernel_launch(void* const* d_in, const int* in_sizes, int n_in,
                              void* d_out, int out_size)
{
    const float* query  = (const float*)d_in[0];
    const float* key_in = (const float*)d_in[1];
    const float* value  = (const float*)d_in[2];
    // d_in[3] = mask (exactly tril -> handled as causal predicate, not read)
    const float* Wq = (const float*)d_in[4];
    const float* bq = (const float*)d_in[5];
    const float* Wk = (const float*)d_in[6];
    const float* bk = (const float*)d_in[7];
    const float* Wv = (const float*)d_in[8];
    const float* bv = (const float*)d_in[9];
    const float* Wo = (const float*)d_in[10];
    const float* bo = (const float*)d_in[11];
    float* out = (float*)d_out;

    float *pq, *pk, *pv, *pa;
    cudaGetSymbolAddress((void**)&pq, g_q);
    cudaGetSymbolAddress((void**)&pk, g_k);
    cudaGetSymbolAddress((void**)&pv, g_v);
    cudaGetSymbolAddress((void**)&pa, g_att);

    dim3 gridP(NE/128, NM/128);   // 8 x 64

    gemm_xwt_kernel<1><<<gridP, 256>>>(query,  Wq, bq, pq, NM, NE, NE);
    gemm_xwt_kernel<1><<<gridP, 256>>>(key_in, Wk, bk, pk, NM, NE, NE);
    gemm_xwt_kernel<1><<<gridP, 256>>>(value,  Wv, bv, pv, NM, NE, NE);

    const int smem_bytes = (4*64*65 + 3*64) * (int)sizeof(float);  // 67328
    cudaFuncSetAttribute(attn_kernel,
                         cudaFuncAttributeMaxDynamicSharedMemorySize, smem_bytes);
    attn_kernel<<<dim3(NT/64, NH, NB), 256, smem_bytes>>>();

    gemm_xwt_kernel<0><<<gridP, 256>>>(pa, Wo, bo, out, NM, NE, NE);
}

// round 3
// speedup vs baseline: 1.7205x; 1.7205x over previous
#include <cuda_runtime.h>
#include <cuda_bf16.h>
#include <math.h>
#include <stdint.h>

#define NB 4
#define NH 16
#define NT 2048
#define NE 1024
#define ND 64
#define NM (NB*NT)   // 8192

// ---------------- scratch (__device__ globals; alloc-free rule) -------------
__device__ float g_q[NB*NH*NT*ND];
__device__ float g_k[NB*NH*NT*ND];
__device__ float g_v[NB*NH*NT*ND];
__device__ float g_att[NB*NT*NE];
__device__ __nv_bfloat16 g_xhi[NM*NE];
__device__ __nv_bfloat16 g_xlo[NM*NE];
__device__ __nv_bfloat16 g_whi[NE*NE];
__device__ __nv_bfloat16 g_wlo[NE*NE];

// ---------------- helpers ----------------------------------------------------
__device__ __forceinline__ uint32_t smem_u32(const void* p) {
    uint32_t a;
    asm("{ .reg .u64 t; cvta.to.shared.u64 t, %1; cvt.u32.u64 %0, t; }" : "=r"(a) : "l"(p));
    return a;
}
__device__ __forceinline__ void ldsm_x4(uint32_t& r0, uint32_t& r1, uint32_t& r2,
                                        uint32_t& r3, uint32_t addr) {
    asm volatile("ldmatrix.sync.aligned.m8n8.x4.shared.b16 {%0,%1,%2,%3}, [%4];"
                 : "=r"(r0), "=r"(r1), "=r"(r2), "=r"(r3) : "r"(addr));
}
__device__ __forceinline__ void mma_bf16(float* c, const uint32_t* a,
                                         uint32_t b0, uint32_t b1) {
    asm volatile(
        "mma.sync.aligned.m16n8k16.row.col.f32.bf16.bf16.f32 "
        "{%0,%1,%2,%3}, {%4,%5,%6,%7}, {%8,%9}, {%0,%1,%2,%3};"
        : "+f"(c[0]), "+f"(c[1]), "+f"(c[2]), "+f"(c[3])
        : "r"(a[0]), "r"(a[1]), "r"(a[2]), "r"(a[3]), "r"(b0), "r"(b1));
}
#define CP_ASYNC16(dst, src) \
    asm volatile("cp.async.cg.shared.global [%0], [%1], 16;" :: "r"(dst), "l"(src))
#define CP_COMMIT() asm volatile("cp.async.commit_group;" ::: "memory")
#define CP_WAIT(n)  asm volatile("cp.async.wait_group %0;" :: "n"(n) : "memory")

// ---------------------------------------------------------------------------
// fp32 -> (bf16 hi, bf16 lo) split conversion, vectorized
// ---------------------------------------------------------------------------
__global__ __launch_bounds__(256) void conv_split(const float4* __restrict__ in,
                                                  uint2* __restrict__ hi,
                                                  uint2* __restrict__ lo, int n4) {
    int i = blockIdx.x * 256 + threadIdx.x;
    if (i >= n4) return;
    float4 v = in[i];
    __nv_bfloat16 hx = __float2bfloat16(v.x), hy = __float2bfloat16(v.y);
    __nv_bfloat16 hz = __float2bfloat16(v.z), hw = __float2bfloat16(v.w);
    __nv_bfloat16 lx = __float2bfloat16(v.x - __bfloat162float(hx));
    __nv_bfloat16 ly = __float2bfloat16(v.y - __bfloat162float(hy));
    __nv_bfloat16 lz = __float2bfloat16(v.z - __bfloat162float(hz));
    __nv_bfloat16 lw = __float2bfloat16(v.w - __bfloat162float(hw));
    __nv_bfloat162 h01(hx, hy), h23(hz, hw), l01(lx, ly), l23(lz, lw);
    uint2 ho, loo;
    ho.x  = *reinterpret_cast<uint32_t*>(&h01); ho.y  = *reinterpret_cast<uint32_t*>(&h23);
    loo.x = *reinterpret_cast<uint32_t*>(&l01); loo.y = *reinterpret_cast<uint32_t*>(&l23);
    hi[i] = ho; lo[i] = loo;
}

// ---------------------------------------------------------------------------
// HMMA bf16x3 GEMM: C = X @ W^T + bias.
// X split (xhi, xlo): [M,K] bf16 row-major; W split (whi, wlo): [N,K] bf16.
// Block 128x128, 8 warps (warp grid 4Mx2N, warp tile 32x64), K-chunk 32,
// cp.async double-buffered smem (pitch 40 elems = conflict-free ldmatrix).
// MODE 0: C[m*NE+n]; MODE 1: scatter to [B,H,T,D].
// ---------------------------------------------------------------------------
#define PITCH_B 80           // bytes per smem row (32 bf16 + 8 pad)
#define MAT_BYTES (128*PITCH_B)   // 10240 per matrix tile
#define STAGE_BYTES (4*MAT_BYTES) // Ahi, Alo, Bhi, Blo
#define NCHUNK (NE/32)       // 32 k-chunks

template<int MODE>
__global__ __launch_bounds__(256) void gemm_mma(
    const __nv_bfloat16* __restrict__ xhi, const __nv_bfloat16* __restrict__ xlo,
    const __nv_bfloat16* __restrict__ whi, const __nv_bfloat16* __restrict__ wlo,
    const float* __restrict__ bias, float* __restrict__ C)
{
    extern __shared__ __align__(256) char smem[];
    const uint32_t sb = smem_u32(smem);
    const int tid = threadIdx.x;
    const int wid = tid >> 5, lane = tid & 31;
    const int wm = wid >> 1, wn = wid & 1;   // 4 x 2 warp grid
    const int n0 = blockIdx.x * 128, m0 = blockIdx.y * 128;

    const __nv_bfloat16* bases[4] = { xhi, xlo, whi, wlo };

    // per-lane ldmatrix byte offsets within one matrix tile
    const int lr = lane & 15;               // row within 16-row group
    const int kb8 = (lane >> 4) << 4;       // +16B for k8..15 half
    uint32_t aoff[2], boff[4];
    #pragma unroll
    for (int i = 0; i < 2; ++i)
        aoff[i] = (uint32_t)((wm*32 + i*16 + lr) * PITCH_B + kb8);
    #pragma unroll
    for (int j = 0; j < 4; ++j)
        boff[j] = (uint32_t)((wn*64 + j*16 + lr) * PITCH_B + kb8);

    float acc[2][8][4];
    #pragma unroll
    for (int i = 0; i < 2; ++i)
        #pragma unroll
        for (int j = 0; j < 8; ++j)
            #pragma unroll
            for (int r = 0; r < 4; ++r) acc[i][j][r] = 0.f;

    // cp.async loader for one stage: 4 matrices x 128 rows x 64B
    auto load_stage = [&](int stage, int kt) {
        const uint32_t sbase = sb + stage * STAGE_BYTES;
        #pragma unroll
        for (int t = 0; t < 4; ++t) {
            #pragma unroll
            for (int it = 0; it < 2; ++it) {
                int idx = tid + it * 256;        // 512 = 128 rows x 4 x16B
                int row = idx >> 2, c16 = idx & 3;
                int rg = ((t < 2) ? m0 : n0) + row;
                const __nv_bfloat16* src = bases[t] + (long)rg * NE + kt + c16 * 8;
                uint32_t dst = sbase + t * MAT_BYTES + row * PITCH_B + c16 * 16;
                CP_ASYNC16(dst, src);
            }
        }
        CP_COMMIT();
    };

    load_stage(0, 0);

    for (int c = 0; c < NCHUNK; ++c) {
        if (c + 1 < NCHUNK) {
            load_stage((c + 1) & 1, (c + 1) * 32);
            CP_WAIT(1);
        } else {
            CP_WAIT(0);
        }
        __syncthreads();

        const uint32_t sA_hi = sb + (c & 1) * STAGE_BYTES;
        const uint32_t sA_lo = sA_hi + MAT_BYTES;
        const uint32_t sB_hi = sA_hi + 2 * MAT_BYTES;
        const uint32_t sB_lo = sA_hi + 3 * MAT_BYTES;

        #pragma unroll
        for (int ks = 0; ks < 2; ++ks) {
            const uint32_t kbyte = ks * 32;   // 16 bf16 = 32B
            uint32_t ah[2][4], al[2][4], bh[4][4], bl[4][4];
            #pragma unroll
            for (int i = 0; i < 2; ++i) {
                ldsm_x4(ah[i][0], ah[i][1], ah[i][2], ah[i][3], sA_hi + aoff[i] + kbyte);
                ldsm_x4(al[i][0], al[i][1], al[i][2], al[i][3], sA_lo + aoff[i] + kbyte);
            }
            #pragma unroll
            for (int j = 0; j < 4; ++j) {
                ldsm_x4(bh[j][0], bh[j][1], bh[j][2], bh[j][3], sB_hi + boff[j] + kbyte);
                ldsm_x4(bl[j][0], bl[j][1], bl[j][2], bl[j][3], sB_lo + boff[j] + kbyte);
            }
            #pragma unroll
            for (int i = 0; i < 2; ++i) {
                #pragma unroll
                for (int j = 0; j < 4; ++j) {
                    // hi*hi
                    mma_bf16(acc[i][2*j],   ah[i], bh[j][0], bh[j][2]);
                    mma_bf16(acc[i][2*j+1], ah[i], bh[j][1], bh[j][3]);
                    // hi*lo
                    mma_bf16(acc[i][2*j],   ah[i], bl[j][0], bl[j][2]);
                    mma_bf16(acc[i][2*j+1], ah[i], bl[j][1], bl[j][3]);
                    // lo*hi
                    mma_bf16(acc[i][2*j],   al[i], bh[j][0], bh[j][2]);
                    mma_bf16(acc[i][2*j+1], al[i], bh[j][1], bh[j][3]);
                }
            }
        }
        __syncthreads();
    }

    // Epilogue: direct float2 stores (c0,c1 are adjacent columns)
    const int qr = lane >> 2, qc = (lane & 3) * 2;
    #pragma unroll
    for (int i = 0; i < 2; ++i) {
        #pragma unroll
        for (int j = 0; j < 8; ++j) {
            const int n = n0 + wn*64 + j*8 + qc;
            const float b0 = bias[n], b1 = bias[n + 1];
            #pragma unroll
            for (int r8 = 0; r8 < 2; ++r8) {
                const int m = m0 + wm*32 + i*16 + qr + r8*8;
                float2 v;
                v.x = acc[i][j][r8*2]     + b0;
                v.y = acc[i][j][r8*2 + 1] + b1;
                if (MODE == 0) {
                    *reinterpret_cast<float2*>(&C[(long)m * NE + n]) = v;
                } else {
                    const int b = m >> 11, t = m & 2047, h = n >> 6, d = n & 63;
                    *reinterpret_cast<float2*>(
                        &C[((((long)(b*NH + h) * NT) + t) << 6) + d]) = v;
                }
            }
        }
    }
}

// ---------------------------------------------------------------------------
// Fused causal flash attention (unchanged from R1 — passing, 2:1 smem-bound)
// ---------------------------------------------------------------------------
__global__ __launch_bounds__(256) void attn_kernel()
{
    extern __shared__ float sm[];
    float* Qs   = sm;
    float* Ks   = Qs + 64*65;
    float* Vs   = Ks + 64*65;
    float* Ps   = Vs + 64*65;
    float* mrow = Ps + 64*65;
    float* lrow = mrow + 64;
    float* crow = lrow + 64;

    const int qt  = blockIdx.x;
    const int h   = blockIdx.y;
    const int b   = blockIdx.z;
    const int tid = threadIdx.x;
    const int tx  = tid & 15, ty = tid >> 4;

    const float* Qg = g_q + ((b*NH + h)*NT + qt*64) * ND;
    const float* Kg = g_k + ((b*NH + h)*NT) * ND;
    const float* Vg = g_v + ((b*NH + h)*NT) * ND;

    for (int idx = tid; idx < 64*64; idx += 256) {
        int r = idx >> 6, d = idx & 63;
        Qs[r*65 + d] = Qg[idx];
    }
    if (tid < 64) { mrow[tid] = -INFINITY; lrow[tid] = 0.f; }

    float oacc[4][4];
    #pragma unroll
    for (int i = 0; i < 4; i++)
        #pragma unroll
        for (int j = 0; j < 4; j++) oacc[i][j] = 0.f;

    const float scale = 0.125f;

    for (int kt = 0; kt <= qt; kt++) {
        __syncthreads();
        const float* Kt = Kg + kt*64*ND;
        const float* Vt = Vg + kt*64*ND;
        for (int idx = tid; idx < 4096; idx += 256) {
            int r = idx >> 6, d = idx & 63;
            Ks[r*65 + d] = Kt[idx];
            Vs[r*65 + d] = Vt[idx];
        }
        __syncthreads();

        float acc[4][4];
        #pragma unroll
        for (int i = 0; i < 4; i++)
            #pragma unroll
            for (int j = 0; j < 4; j++) acc[i][j] = 0.f;

        #pragma unroll 8
        for (int d = 0; d < 64; d++) {
            float qv[4], kv[4];
            #pragma unroll
            for (int i = 0; i < 4; i++) qv[i] = Qs[(ty + 16*i)*65 + d];
            #pragma unroll
            for (int j = 0; j < 4; j++) kv[j] = Ks[(tx + 16*j)*65 + d];
            #pragma unroll
            for (int i = 0; i < 4; i++)
                #pragma unroll
                for (int j = 0; j < 4; j++)
                    acc[i][j] += qv[i]*kv[j];
        }

        const bool diag = (kt == qt);
        #pragma unroll
        for (int i = 0; i < 4; i++) {
            int r = ty + 16*i;
            #pragma unroll
            for (int j = 0; j < 4; j++) {
                int c = tx + 16*j;
                float s = acc[i][j] * scale;
                if (diag && c > r) s = -INFINITY;
                Ps[r*65 + c] = s;
            }
        }
        __syncthreads();

        if (tid < 64) {
            const int r = tid;
            float mold = mrow[r];
            float mx = mold;
            #pragma unroll 8
            for (int c = 0; c < 64; c++) mx = fmaxf(mx, Ps[r*65 + c]);
            float corr = __expf(mold - mx);
            float sum = 0.f;
            #pragma unroll 8
            for (int c = 0; c < 64; c++) {
                float p = __expf(Ps[r*65 + c] - mx);
                Ps[r*65 + c] = p;
                sum += p;
            }
            lrow[r] = lrow[r]*corr + sum;
            mrow[r] = mx;
            crow[r] = corr;
        }
        __syncthreads();

        float cr[4];
        #pragma unroll
        for (int i = 0; i < 4; i++) cr[i] = crow[ty + 16*i];
        #pragma unroll
        for (int i = 0; i < 4; i++)
            #pragma unroll
            for (int j = 0; j < 4; j++) oacc[i][j] *= cr[i];

        #pragma unroll 8
        for (int kk = 0; kk < 64; kk++) {
            float pv[4], vv[4];
            #pragma unroll
            for (int i = 0; i < 4; i++) pv[i] = Ps[(ty + 16*i)*65 + kk];
            #pragma unroll
            for (int j = 0; j < 4; j++) vv[j] = Vs[kk*65 + tx + 16*j];
            #pragma unroll
            for (int i = 0; i < 4; i++)
                #pragma unroll
                for (int j = 0; j < 4; j++)
                    oacc[i][j] += pv[i]*vv[j];
        }
    }

    float li[4];
    #pragma unroll
    for (int i = 0; i < 4; i++) li[i] = 1.f / lrow[ty + 16*i];
    #pragma unroll
    for (int i = 0; i < 4; i++) {
        int t = qt*64 + ty + 16*i;
        #pragma unroll
        for (int j = 0; j < 4; j++) {
            int c = tx + 16*j;
            g_att[(b*NT + t)*NE + h*ND + c] = oacc[i][j] * li[i];
        }
    }
}

// ---------------------------------------------------------------------------
extern "C" void kernel_launch(void* const* d_in, const int* in_sizes, int n_in,
                              void* d_out, int out_size)
{
    const float* query  = (const float*)d_in[0];
    const float* key_in = (const float*)d_in[1];
    const float* value  = (const float*)d_in[2];
    // d_in[3] = mask (exact tril -> causal predicate, not read)
    const float* Wq = (const float*)d_in[4];
    const float* bq = (const float*)d_in[5];
    const float* Wk = (const float*)d_in[6];
    const float* bk = (const float*)d_in[7];
    const float* Wv = (const float*)d_in[8];
    const float* bv = (const float*)d_in[9];
    const float* Wo = (const float*)d_in[10];
    const float* bo = (const float*)d_in[11];
    float* out = (float*)d_out;

    float *pq, *pk, *pv, *pa;
    cudaGetSymbolAddress((void**)&pq, g_q);
    cudaGetSymbolAddress((void**)&pk, g_k);
    cudaGetSymbolAddress((void**)&pv, g_v);
    cudaGetSymbolAddress((void**)&pa, g_att);
    __nv_bfloat16 *xhi, *xlo, *whi, *wlo;
    cudaGetSymbolAddress((void**)&xhi, g_xhi);
    cudaGetSymbolAddress((void**)&xlo, g_xlo);
    cudaGetSymbolAddress((void**)&whi, g_whi);
    cudaGetSymbolAddress((void**)&wlo, g_wlo);

    const int gemm_smem = 2 * STAGE_BYTES;   // 81920
    cudaFuncSetAttribute(gemm_mma<0>, cudaFuncAttributeMaxDynamicSharedMemorySize, gemm_smem);
    cudaFuncSetAttribute(gemm_mma<1>, cudaFuncAttributeMaxDynamicSharedMemorySize, gemm_smem);

    const int n4x = NM * NE / 4;
    const int n4w = NE * NE / 4;
    dim3 gridG(NE / 128, NM / 128);  // 8 x 64

    conv_split<<<n4x / 256, 256>>>((const float4*)query, (uint2*)xhi, (uint2*)xlo, n4x);
    conv_split<<<n4w / 256, 256>>>((const float4*)Wq, (uint2*)whi, (uint2*)wlo, n4w);
    gemm_mma<1><<<gridG, 256, gemm_smem>>>(xhi, xlo, whi, wlo, bq, pq);

    conv_split<<<n4x / 256, 256>>>((const float4*)key_in, (uint2*)xhi, (uint2*)xlo, n4x);
    conv_split<<<n4w / 256, 256>>>((const float4*)Wk, (uint2*)whi, (uint2*)wlo, n4w);
    gemm_mma<1><<<gridG, 256, gemm_smem>>>(xhi, xlo, whi, wlo, bk, pk);

    conv_split<<<n4x / 256, 256>>>((const float4*)value, (uint2*)xhi, (uint2*)xlo, n4x);
    conv_split<<<n4w / 256, 256>>>((const float4*)Wv, (uint2*)whi, (uint2*)wlo, n4w);
    gemm_mma<1><<<gridG, 256, gemm_smem>>>(xhi, xlo, whi, wlo, bv, pv);

    const int attn_smem = (4*64*65 + 3*64) * (int)sizeof(float);
    cudaFuncSetAttribute(attn_kernel, cudaFuncAttributeMaxDynamicSharedMemorySize, attn_smem);
    attn_kernel<<<dim3(NT/64, NH, NB), 256, attn_smem>>>();

    conv_split<<<n4x / 256, 256>>>((const float4*)pa, (uint2*)xhi, (uint2*)xlo, n4x);
    conv_split<<<n4w / 256, 256>>>((const float4*)Wo, (uint2*)whi, (uint2*)wlo, n4w);
    gemm_mma<0><<<gridG, 256, gemm_smem>>>(xhi, xlo, whi, wlo, bo, out);
}

// round 4
// speedup vs baseline: 2.8215x; 1.6399x over previous
#include <cuda_runtime.h>
#include <cuda_bf16.h>
#include <math.h>
#include <stdint.h>

#define NB 4
#define NH 16
#define NT 2048
#define NE 1024
#define ND 64
#define NM (NB*NT)   // 8192

// ---------------- scratch (__device__ globals; alloc-free rule) -------------
__device__ float g_q[NB*NH*NT*ND];
__device__ float g_k[NB*NH*NT*ND];
__device__ float g_v[NB*NH*NT*ND];
__device__ float g_att[NB*NT*NE];
__device__ __nv_bfloat16 g_xhi[NM*NE];
__device__ __nv_bfloat16 g_xlo[NM*NE];
__device__ __nv_bfloat16 g_whi[NE*NE];
__device__ __nv_bfloat16 g_wlo[NE*NE];

// ---------------- helpers ----------------------------------------------------
__device__ __forceinline__ uint32_t smem_u32(const void* p) {
    uint32_t a;
    asm("{ .reg .u64 t; cvta.to.shared.u64 t, %1; cvt.u32.u64 %0, t; }" : "=r"(a) : "l"(p));
    return a;
}
__device__ __forceinline__ void ldsm_x4(uint32_t& r0, uint32_t& r1, uint32_t& r2,
                                        uint32_t& r3, uint32_t addr) {
    asm volatile("ldmatrix.sync.aligned.m8n8.x4.shared.b16 {%0,%1,%2,%3}, [%4];"
                 : "=r"(r0), "=r"(r1), "=r"(r2), "=r"(r3) : "r"(addr));
}
__device__ __forceinline__ void mma_bf16(float* c, const uint32_t* a,
                                         uint32_t b0, uint32_t b1) {
    asm volatile(
        "mma.sync.aligned.m16n8k16.row.col.f32.bf16.bf16.f32 "
        "{%0,%1,%2,%3}, {%4,%5,%6,%7}, {%8,%9}, {%0,%1,%2,%3};"
        : "+f"(c[0]), "+f"(c[1]), "+f"(c[2]), "+f"(c[3])
        : "r"(a[0]), "r"(a[1]), "r"(a[2]), "r"(a[3]), "r"(b0), "r"(b1));
}
__device__ __forceinline__ uint32_t pack_bf16(float x, float y) {
    __nv_bfloat162 t = __floats2bfloat162_rn(x, y);
    return *reinterpret_cast<uint32_t*>(&t);
}
#define CP_ASYNC16(dst, src) \
    asm volatile("cp.async.cg.shared.global [%0], [%1], 16;" :: "r"(dst), "l"(src))
#define CP_COMMIT() asm volatile("cp.async.commit_group;" ::: "memory")
#define CP_WAIT(n)  asm volatile("cp.async.wait_group %0;" :: "n"(n) : "memory")

// ---------------------------------------------------------------------------
// fp32 -> (bf16 hi, bf16 lo) split conversion
// ---------------------------------------------------------------------------
__global__ __launch_bounds__(256) void conv_split(const float4* __restrict__ in,
                                                  uint2* __restrict__ hi,
                                                  uint2* __restrict__ lo, int n4) {
    int i = blockIdx.x * 256 + threadIdx.x;
    if (i >= n4) return;
    float4 v = in[i];
    __nv_bfloat16 hx = __float2bfloat16(v.x), hy = __float2bfloat16(v.y);
    __nv_bfloat16 hz = __float2bfloat16(v.z), hw = __float2bfloat16(v.w);
    __nv_bfloat16 lx = __float2bfloat16(v.x - __bfloat162float(hx));
    __nv_bfloat16 ly = __float2bfloat16(v.y - __bfloat162float(hy));
    __nv_bfloat16 lz = __float2bfloat16(v.z - __bfloat162float(hz));
    __nv_bfloat16 lw = __float2bfloat16(v.w - __bfloat162float(hw));
    __nv_bfloat162 h01(hx, hy), h23(hz, hw), l01(lx, ly), l23(lz, lw);
    uint2 ho, loo;
    ho.x  = *reinterpret_cast<uint32_t*>(&h01); ho.y  = *reinterpret_cast<uint32_t*>(&h23);
    loo.x = *reinterpret_cast<uint32_t*>(&l01); loo.y = *reinterpret_cast<uint32_t*>(&l23);
    hi[i] = ho; lo[i] = loo;
}

// ---------------------------------------------------------------------------
// HMMA bf16x3 GEMM (unchanged from R3 — passing)
// ---------------------------------------------------------------------------
#define PITCH_B 80
#define MAT_BYTES (128*PITCH_B)
#define STAGE_BYTES (4*MAT_BYTES)
#define NCHUNK (NE/32)

template<int MODE>
__global__ __launch_bounds__(256) void gemm_mma(
    const __nv_bfloat16* __restrict__ xhi, const __nv_bfloat16* __restrict__ xlo,
    const __nv_bfloat16* __restrict__ whi, const __nv_bfloat16* __restrict__ wlo,
    const float* __restrict__ bias, float* __restrict__ C)
{
    extern __shared__ __align__(256) char smem[];
    const uint32_t sb = smem_u32(smem);
    const int tid = threadIdx.x;
    const int wid = tid >> 5, lane = tid & 31;
    const int wm = wid >> 1, wn = wid & 1;
    const int n0 = blockIdx.x * 128, m0 = blockIdx.y * 128;

    const __nv_bfloat16* bases[4] = { xhi, xlo, whi, wlo };

    const int lr = lane & 15;
    const int kb8 = (lane >> 4) << 4;
    uint32_t aoff[2], boff[4];
    #pragma unroll
    for (int i = 0; i < 2; ++i)
        aoff[i] = (uint32_t)((wm*32 + i*16 + lr) * PITCH_B + kb8);
    #pragma unroll
    for (int j = 0; j < 4; ++j)
        boff[j] = (uint32_t)((wn*64 + j*16 + lr) * PITCH_B + kb8);

    float acc[2][8][4];
    #pragma unroll
    for (int i = 0; i < 2; ++i)
        #pragma unroll
        for (int j = 0; j < 8; ++j)
            #pragma unroll
            for (int r = 0; r < 4; ++r) acc[i][j][r] = 0.f;

    auto load_stage = [&](int stage, int kt) {
        const uint32_t sbase = sb + stage * STAGE_BYTES;
        #pragma unroll
        for (int t = 0; t < 4; ++t) {
            #pragma unroll
            for (int it = 0; it < 2; ++it) {
                int idx = tid + it * 256;
                int row = idx >> 2, c16 = idx & 3;
                int rg = ((t < 2) ? m0 : n0) + row;
                const __nv_bfloat16* src = bases[t] + (long)rg * NE + kt + c16 * 8;
                uint32_t dst = sbase + t * MAT_BYTES + row * PITCH_B + c16 * 16;
                CP_ASYNC16(dst, src);
            }
        }
        CP_COMMIT();
    };

    load_stage(0, 0);

    for (int c = 0; c < NCHUNK; ++c) {
        if (c + 1 < NCHUNK) {
            load_stage((c + 1) & 1, (c + 1) * 32);
            CP_WAIT(1);
        } else {
            CP_WAIT(0);
        }
        __syncthreads();

        const uint32_t sA_hi = sb + (c & 1) * STAGE_BYTES;
        const uint32_t sA_lo = sA_hi + MAT_BYTES;
        const uint32_t sB_hi = sA_hi + 2 * MAT_BYTES;
        const uint32_t sB_lo = sA_hi + 3 * MAT_BYTES;

        #pragma unroll
        for (int ks = 0; ks < 2; ++ks) {
            const uint32_t kbyte = ks * 32;
            uint32_t ah[2][4], al[2][4], bh[4][4], bl[4][4];
            #pragma unroll
            for (int i = 0; i < 2; ++i) {
                ldsm_x4(ah[i][0], ah[i][1], ah[i][2], ah[i][3], sA_hi + aoff[i] + kbyte);
                ldsm_x4(al[i][0], al[i][1], al[i][2], al[i][3], sA_lo + aoff[i] + kbyte);
            }
            #pragma unroll
            for (int j = 0; j < 4; ++j) {
                ldsm_x4(bh[j][0], bh[j][1], bh[j][2], bh[j][3], sB_hi + boff[j] + kbyte);
                ldsm_x4(bl[j][0], bl[j][1], bl[j][2], bl[j][3], sB_lo + boff[j] + kbyte);
            }
            #pragma unroll
            for (int i = 0; i < 2; ++i) {
                #pragma unroll
                for (int j = 0; j < 4; ++j) {
                    mma_bf16(acc[i][2*j],   ah[i], bh[j][0], bh[j][2]);
                    mma_bf16(acc[i][2*j+1], ah[i], bh[j][1], bh[j][3]);
                    mma_bf16(acc[i][2*j],   ah[i], bl[j][0], bl[j][2]);
                    mma_bf16(acc[i][2*j+1], ah[i], bl[j][1], bl[j][3]);
                    mma_bf16(acc[i][2*j],   al[i], bh[j][0], bh[j][2]);
                    mma_bf16(acc[i][2*j+1], al[i], bh[j][1], bh[j][3]);
                }
            }
        }
        __syncthreads();
    }

    const int qr = lane >> 2, qc = (lane & 3) * 2;
    #pragma unroll
    for (int i = 0; i < 2; ++i) {
        #pragma unroll
        for (int j = 0; j < 8; ++j) {
            const int n = n0 + wn*64 + j*8 + qc;
            const float b0 = bias[n], b1 = bias[n + 1];
            #pragma unroll
            for (int r8 = 0; r8 < 2; ++r8) {
                const int m = m0 + wm*32 + i*16 + qr + r8*8;
                float2 v;
                v.x = acc[i][j][r8*2]     + b0;
                v.y = acc[i][j][r8*2 + 1] + b1;
                if (MODE == 0) {
                    *reinterpret_cast<float2*>(&C[(long)m * NE + n]) = v;
                } else {
                    const int b = m >> 11, t = m & 2047, h = n >> 6, d = n & 63;
                    *reinterpret_cast<float2*>(
                        &C[((((long)(b*NH + h) * NT) + t) << 6) + d]) = v;
                }
            }
        }
    }
}

// ---------------------------------------------------------------------------
// Tensor-core causal flash attention (bf16x3).
// CTA: 128 q-rows x (head, batch). 8 warps, each 16 q-rows x 64 kv-cols.
// Q,K,V converted fp32->bf16 hi/lo in-kernel (scale folded into Q);
// V stored transposed [d][pos] in smem for the PV B-operand.
// ---------------------------------------------------------------------------
#define APITCH 144                 // smem row pitch (64 bf16 = 128B + 16 pad)
#define OFF_QH 0
#define OFF_QL (128*APITCH)        // 18432
#define OFF_KH (2*128*APITCH)      // 36864
#define OFF_KL (OFF_KH + 64*APITCH)
#define OFF_VH (OFF_KL + 64*APITCH)
#define OFF_VL (OFF_VH + 64*APITCH)
#define ATTN_SMEM (OFF_VL + 64*APITCH)   // 73728

__global__ __launch_bounds__(256) void attn_mma()
{
    extern __shared__ __align__(256) char smem[];
    const uint32_t sb = smem_u32(smem);
    const int tid = threadIdx.x, wid = tid >> 5, lane = tid & 31;
    const int qt = blockIdx.x;          // 16 q-tiles of 128 rows
    const int h = blockIdx.y, b = blockIdx.z;

    const float* Qg = g_q + ((long)(b*NH + h)*NT + qt*128) * ND;
    const float* Kg = g_k + (long)(b*NH + h)*NT * ND;
    const float* Vg = g_v + (long)(b*NH + h)*NT * ND;

    // ---- load Q once (scale folded), split hi/lo ----
    for (int i = tid; i < 2048; i += 256) {          // 2048 float4 = 128x64
        int row = i >> 4, d4 = i & 15;
        float4 v = reinterpret_cast<const float4*>(Qg)[i];
        v.x *= 0.125f; v.y *= 0.125f; v.z *= 0.125f; v.w *= 0.125f;
        __nv_bfloat162 h01 = __floats2bfloat162_rn(v.x, v.y);
        __nv_bfloat162 h23 = __floats2bfloat162_rn(v.z, v.w);
        __nv_bfloat162 l01 = __floats2bfloat162_rn(v.x - __low2float(h01),
                                                   v.y - __high2float(h01));
        __nv_bfloat162 l23 = __floats2bfloat162_rn(v.z - __low2float(h23),
                                                   v.w - __high2float(h23));
        uint2* dh = reinterpret_cast<uint2*>(smem + OFF_QH + row*APITCH + d4*8);
        uint2* dl = reinterpret_cast<uint2*>(smem + OFF_QL + row*APITCH + d4*8);
        *dh = make_uint2(*reinterpret_cast<uint32_t*>(&h01), *reinterpret_cast<uint32_t*>(&h23));
        *dl = make_uint2(*reinterpret_cast<uint32_t*>(&l01), *reinterpret_cast<uint32_t*>(&l23));
    }

    const int lr = lane & 15;
    const int kb8 = (lane >> 4) << 4;
    const uint32_t aoffQ = (uint32_t)((wid*16 + lr) * APITCH + kb8);
    const uint32_t boff  = (uint32_t)(lr * APITCH + kb8);

    float m0 = -INFINITY, m1 = -INFINITY, l0 = 0.f, l1 = 0.f;
    float o[8][4];
    #pragma unroll
    for (int j = 0; j < 8; ++j)
        #pragma unroll
        for (int r = 0; r < 4; ++r) o[j][r] = 0.f;

    const int nkt = 2*qt + 2;
    const int rowg0 = qt*128 + wid*16 + (lane >> 2);
    const int qc2 = (lane & 3) * 2;

    for (int kt = 0; kt < nkt; ++kt) {
        __syncthreads();
        // ---- load K,V tile (64x64 fp32), split, V transposed ----
        const float4* K4 = reinterpret_cast<const float4*>(Kg + (long)kt*64*ND);
        const float4* V4 = reinterpret_cast<const float4*>(Vg + (long)kt*64*ND);
        for (int i = tid; i < 1024; i += 256) {
            int row = i >> 4, d4 = i & 15;
            float4 kv = K4[i];
            __nv_bfloat162 h01 = __floats2bfloat162_rn(kv.x, kv.y);
            __nv_bfloat162 h23 = __floats2bfloat162_rn(kv.z, kv.w);
            __nv_bfloat162 l01 = __floats2bfloat162_rn(kv.x - __low2float(h01),
                                                       kv.y - __high2float(h01));
            __nv_bfloat162 l23 = __floats2bfloat162_rn(kv.z - __low2float(h23),
                                                       kv.w - __high2float(h23));
            *reinterpret_cast<uint2*>(smem + OFF_KH + row*APITCH + d4*8) =
                make_uint2(*reinterpret_cast<uint32_t*>(&h01), *reinterpret_cast<uint32_t*>(&h23));
            *reinterpret_cast<uint2*>(smem + OFF_KL + row*APITCH + d4*8) =
                make_uint2(*reinterpret_cast<uint32_t*>(&l01), *reinterpret_cast<uint32_t*>(&l23));

            float4 vv = V4[i];
            float vf[4] = { vv.x, vv.y, vv.z, vv.w };
            #pragma unroll
            for (int e = 0; e < 4; ++e) {
                int d = d4*4 + e;
                __nv_bfloat16 vh = __float2bfloat16(vf[e]);
                __nv_bfloat16 vl = __float2bfloat16(vf[e] - __bfloat162float(vh));
                *reinterpret_cast<__nv_bfloat16*>(smem + OFF_VH + d*APITCH + row*2) = vh;
                *reinterpret_cast<__nv_bfloat16*>(smem + OFF_VL + d*APITCH + row*2) = vl;
            }
        }
        __syncthreads();

        // ---- S = Q @ K^T (bf16x3) ----
        float s[8][4];
        #pragma unroll
        for (int j = 0; j < 8; ++j)
            #pragma unroll
            for (int r = 0; r < 4; ++r) s[j][r] = 0.f;

        #pragma unroll
        for (int ks = 0; ks < 4; ++ks) {
            const uint32_t kb = ks * 32;
            uint32_t ah[4], al[4];
            ldsm_x4(ah[0], ah[1], ah[2], ah[3], sb + OFF_QH + aoffQ + kb);
            ldsm_x4(al[0], al[1], al[2], al[3], sb + OFF_QL + aoffQ + kb);
            #pragma unroll
            for (int t = 0; t < 4; ++t) {
                uint32_t bh[4], bl[4];
                ldsm_x4(bh[0], bh[1], bh[2], bh[3], sb + OFF_KH + boff + t*16*APITCH + kb);
                ldsm_x4(bl[0], bl[1], bl[2], bl[3], sb + OFF_KL + boff + t*16*APITCH + kb);
                mma_bf16(s[2*t],   ah, bh[0], bh[2]);
                mma_bf16(s[2*t+1], ah, bh[1], bh[3]);
                mma_bf16(s[2*t],   ah, bl[0], bl[2]);
                mma_bf16(s[2*t+1], ah, bl[1], bl[3]);
                mma_bf16(s[2*t],   al, bh[0], bh[2]);
                mma_bf16(s[2*t+1], al, bh[1], bh[3]);
            }
        }

        // ---- causal mask (only diagonal-straddling tiles) ----
        if (kt >= 2*qt) {
            const int colbase = kt*64 + qc2;
            #pragma unroll
            for (int j = 0; j < 8; ++j) {
                int c0 = colbase + j*8, c1 = c0 + 1;
                if (c0 > rowg0)     s[j][0] = -1e30f;
                if (c1 > rowg0)     s[j][1] = -1e30f;
                if (c0 > rowg0 + 8) s[j][2] = -1e30f;
                if (c1 > rowg0 + 8) s[j][3] = -1e30f;
            }
        }

        // ---- streaming softmax (registers + quad shuffles) ----
        float rm0 = -1e30f, rm1 = -1e30f;
        #pragma unroll
        for (int j = 0; j < 8; ++j) {
            rm0 = fmaxf(rm0, fmaxf(s[j][0], s[j][1]));
            rm1 = fmaxf(rm1, fmaxf(s[j][2], s[j][3]));
        }
        rm0 = fmaxf(rm0, __shfl_xor_sync(0xffffffffu, rm0, 1));
        rm0 = fmaxf(rm0, __shfl_xor_sync(0xffffffffu, rm0, 2));
        rm1 = fmaxf(rm1, __shfl_xor_sync(0xffffffffu, rm1, 1));
        rm1 = fmaxf(rm1, __shfl_xor_sync(0xffffffffu, rm1, 2));
        const float mn0 = fmaxf(m0, rm0), mn1 = fmaxf(m1, rm1);
        const float cr0 = __expf(m0 - mn0), cr1 = __expf(m1 - mn1);
        float sum0 = 0.f, sum1 = 0.f;
        #pragma unroll
        for (int j = 0; j < 8; ++j) {
            s[j][0] = __expf(s[j][0] - mn0);
            s[j][1] = __expf(s[j][1] - mn0);
            s[j][2] = __expf(s[j][2] - mn1);
            s[j][3] = __expf(s[j][3] - mn1);
            sum0 += s[j][0] + s[j][1];
            sum1 += s[j][2] + s[j][3];
        }
        sum0 += __shfl_xor_sync(0xffffffffu, sum0, 1);
        sum0 += __shfl_xor_sync(0xffffffffu, sum0, 2);
        sum1 += __shfl_xor_sync(0xffffffffu, sum1, 1);
        sum1 += __shfl_xor_sync(0xffffffffu, sum1, 2);
        l0 = l0*cr0 + sum0; l1 = l1*cr1 + sum1;
        m0 = mn0; m1 = mn1;
        #pragma unroll
        for (int j = 0; j < 8; ++j) {
            o[j][0] *= cr0; o[j][1] *= cr0;
            o[j][2] *= cr1; o[j][3] *= cr1;
        }

        // ---- O += P @ V (bf16x3, P split in-register) ----
        #pragma unroll
        for (int ks = 0; ks < 4; ++ks) {
            uint32_t ph[4], pl[4];
            {
                const float* r0 = s[2*ks];
                const float* r1 = s[2*ks+1];
                ph[0] = pack_bf16(r0[0], r0[1]);
                ph[1] = pack_bf16(r0[2], r0[3]);
                ph[2] = pack_bf16(r1[0], r1[1]);
                ph[3] = pack_bf16(r1[2], r1[3]);
                __nv_bfloat162 t0 = *reinterpret_cast<__nv_bfloat162*>(&ph[0]);
                __nv_bfloat162 t1 = *reinterpret_cast<__nv_bfloat162*>(&ph[1]);
                __nv_bfloat162 t2 = *reinterpret_cast<__nv_bfloat162*>(&ph[2]);
                __nv_bfloat162 t3 = *reinterpret_cast<__nv_bfloat162*>(&ph[3]);
                pl[0] = pack_bf16(r0[0] - __low2float(t0), r0[1] - __high2float(t0));
                pl[1] = pack_bf16(r0[2] - __low2float(t1), r0[3] - __high2float(t1));
                pl[2] = pack_bf16(r1[0] - __low2float(t2), r1[1] - __high2float(t2));
                pl[3] = pack_bf16(r1[2] - __low2float(t3), r1[3] - __high2float(t3));
            }
            const uint32_t kb = ks * 32;
            #pragma unroll
            for (int t = 0; t < 4; ++t) {
                uint32_t vh[4], vl[4];
                ldsm_x4(vh[0], vh[1], vh[2], vh[3], sb + OFF_VH + boff + t*16*APITCH + kb);
                ldsm_x4(vl[0], vl[1], vl[2], vl[3], sb + OFF_VL + boff + t*16*APITCH + kb);
                mma_bf16(o[2*t],   ph, vh[0], vh[2]);
                mma_bf16(o[2*t+1], ph, vh[1], vh[3]);
                mma_bf16(o[2*t],   ph, vl[0], vl[2]);
                mma_bf16(o[2*t+1], ph, vl[1], vl[3]);
                mma_bf16(o[2*t],   pl, vh[0], vh[2]);
                mma_bf16(o[2*t+1], pl, vh[1], vh[3]);
            }
        }
    }

    // ---- finalize: O /= l, write [B,T,E] ----
    const float il0 = 1.f / l0, il1 = 1.f / l1;
    const int t0 = qt*128 + wid*16 + (lane >> 2);
    float* outp = g_att + ((long)b*NT)*NE + (long)h*64;
    #pragma unroll
    for (int j = 0; j < 8; ++j) {
        const int d = j*8 + qc2;
        float2 v0 = make_float2(o[j][0]*il0, o[j][1]*il0);
        float2 v1 = make_float2(o[j][2]*il1, o[j][3]*il1);
        *reinterpret_cast<float2*>(&outp[(long)t0*NE + d]) = v0;
        *reinterpret_cast<float2*>(&outp[(long)(t0+8)*NE + d]) = v1;
    }
}

// ---------------------------------------------------------------------------
extern "C" void kernel_launch(void* const* d_in, const int* in_sizes, int n_in,
                              void* d_out, int out_size)
{
    const float* query  = (const float*)d_in[0];
    const float* key_in = (const float*)d_in[1];
    const float* value  = (const float*)d_in[2];
    // d_in[3] = mask (exact tril -> causal predicate, not read)
    const float* Wq = (const float*)d_in[4];
    const float* bq = (const float*)d_in[5];
    const float* Wk = (const float*)d_in[6];
    const float* bk = (const float*)d_in[7];
    const float* Wv = (const float*)d_in[8];
    const float* bv = (const float*)d_in[9];
    const float* Wo = (const float*)d_in[10];
    const float* bo = (const float*)d_in[11];
    float* out = (float*)d_out;

    float *pq, *pk, *pv, *pa;
    cudaGetSymbolAddress((void**)&pq, g_q);
    cudaGetSymbolAddress((void**)&pk, g_k);
    cudaGetSymbolAddress((void**)&pv, g_v);
    cudaGetSymbolAddress((void**)&pa, g_att);
    __nv_bfloat16 *xhi, *xlo, *whi, *wlo;
    cudaGetSymbolAddress((void**)&xhi, g_xhi);
    cudaGetSymbolAddress((void**)&xlo, g_xlo);
    cudaGetSymbolAddress((void**)&whi, g_whi);
    cudaGetSymbolAddress((void**)&wlo, g_wlo);

    const int gemm_smem = 2 * STAGE_BYTES;   // 81920
    cudaFuncSetAttribute(gemm_mma<0>, cudaFuncAttributeMaxDynamicSharedMemorySize, gemm_smem);
    cudaFuncSetAttribute(gemm_mma<1>, cudaFuncAttributeMaxDynamicSharedMemorySize, gemm_smem);
    cudaFuncSetAttribute(attn_mma, cudaFuncAttributeMaxDynamicSharedMemorySize, ATTN_SMEM);

    const int n4x = NM * NE / 4;
    const int n4w = NE * NE / 4;
    dim3 gridG(NE / 128, NM / 128);

    conv_split<<<n4x / 256, 256>>>((const float4*)query, (uint2*)xhi, (uint2*)xlo, n4x);
    conv_split<<<n4w / 256, 256>>>((const float4*)Wq, (uint2*)whi, (uint2*)wlo, n4w);
    gemm_mma<1><<<gridG, 256, gemm_smem>>>(xhi, xlo, whi, wlo, bq, pq);

    conv_split<<<n4x / 256, 256>>>((const float4*)key_in, (uint2*)xhi, (uint2*)xlo, n4x);
    conv_split<<<n4w / 256, 256>>>((const float4*)Wk, (uint2*)whi, (uint2*)wlo, n4w);
    gemm_mma<1><<<gridG, 256, gemm_smem>>>(xhi, xlo, whi, wlo, bk, pk);

    conv_split<<<n4x / 256, 256>>>((const float4*)value, (uint2*)xhi, (uint2*)xlo, n4x);
    conv_split<<<n4w / 256, 256>>>((const float4*)Wv, (uint2*)whi, (uint2*)wlo, n4w);
    gemm_mma<1><<<gridG, 256, gemm_smem>>>(xhi, xlo, whi, wlo, bv, pv);

    attn_mma<<<dim3(16, NH, NB), 256, ATTN_SMEM>>>();

    conv_split<<<n4x / 256, 256>>>((const float4*)pa, (uint2*)xhi, (uint2*)xlo, n4x);
    conv_split<<<n4w / 256, 256>>>((const float4*)Wo, (uint2*)whi, (uint2*)wlo, n4w);
    gemm_mma<0><<<gridG, 256, gemm_smem>>>(xhi, xlo, whi, wlo, bo, out);
}

// round 5
// speedup vs baseline: 3.2167x; 1.1401x over previous
#include <cuda_runtime.h>
#include <cuda_bf16.h>
#include <math.h>
#include <stdint.h>

#define NB 4
#define NH 16
#define NT 2048
#define NE 1024
#define ND 64
#define NM (NB*NT)   // 8192

// ---------------- scratch (__device__ globals; alloc-free rule) -------------
__device__ __nv_bfloat16 g_qhi[NB*NH*NT*ND];
__device__ __nv_bfloat16 g_qlo[NB*NH*NT*ND];
__device__ __nv_bfloat16 g_khi[NB*NH*NT*ND];
__device__ __nv_bfloat16 g_klo[NB*NH*NT*ND];
__device__ __nv_bfloat16 g_vhi[NB*NH*NT*ND];
__device__ __nv_bfloat16 g_vlo[NB*NH*NT*ND];
__device__ __nv_bfloat16 g_xhi[NM*NE];
__device__ __nv_bfloat16 g_xlo[NM*NE];
__device__ __nv_bfloat16 g_whi[NE*NE];
__device__ __nv_bfloat16 g_wlo[NE*NE];

// ---------------- helpers ----------------------------------------------------
__device__ __forceinline__ uint32_t smem_u32(const void* p) {
    uint32_t a;
    asm("{ .reg .u64 t; cvta.to.shared.u64 t, %1; cvt.u32.u64 %0, t; }" : "=r"(a) : "l"(p));
    return a;
}
__device__ __forceinline__ void ldsm_x4(uint32_t& r0, uint32_t& r1, uint32_t& r2,
                                        uint32_t& r3, uint32_t addr) {
    asm volatile("ldmatrix.sync.aligned.m8n8.x4.shared.b16 {%0,%1,%2,%3}, [%4];"
                 : "=r"(r0), "=r"(r1), "=r"(r2), "=r"(r3) : "r"(addr));
}
__device__ __forceinline__ void ldsm_x4_t(uint32_t& r0, uint32_t& r1, uint32_t& r2,
                                          uint32_t& r3, uint32_t addr) {
    asm volatile("ldmatrix.sync.aligned.m8n8.x4.trans.shared.b16 {%0,%1,%2,%3}, [%4];"
                 : "=r"(r0), "=r"(r1), "=r"(r2), "=r"(r3) : "r"(addr));
}
__device__ __forceinline__ void mma_bf16(float* c, const uint32_t* a,
                                         uint32_t b0, uint32_t b1) {
    asm volatile(
        "mma.sync.aligned.m16n8k16.row.col.f32.bf16.bf16.f32 "
        "{%0,%1,%2,%3}, {%4,%5,%6,%7}, {%8,%9}, {%0,%1,%2,%3};"
        : "+f"(c[0]), "+f"(c[1]), "+f"(c[2]), "+f"(c[3])
        : "r"(a[0]), "r"(a[1]), "r"(a[2]), "r"(a[3]), "r"(b0), "r"(b1));
}
__device__ __forceinline__ uint32_t pack_bf16(float x, float y) {
    __nv_bfloat162 t = __floats2bfloat162_rn(x, y);
    return *reinterpret_cast<uint32_t*>(&t);
}
__device__ __forceinline__ void split2(float x, float y, uint32_t& h, uint32_t& l) {
    __nv_bfloat162 hh = __floats2bfloat162_rn(x, y);
    h = *reinterpret_cast<uint32_t*>(&hh);
    l = pack_bf16(x - __low2float(hh), y - __high2float(hh));
}
#define CP_ASYNC16(dst, src) \
    asm volatile("cp.async.cg.shared.global [%0], [%1], 16;" :: "r"(dst), "l"(src))
#define CP_COMMIT() asm volatile("cp.async.commit_group;" ::: "memory")
#define CP_WAIT(n)  asm volatile("cp.async.wait_group %0;" :: "n"(n) : "memory")

// ---------------------------------------------------------------------------
// fp32 -> (bf16 hi, bf16 lo) split conversion (inputs & weights for GEMMs)
// ---------------------------------------------------------------------------
__global__ __launch_bounds__(256) void conv_split(const float4* __restrict__ in,
                                                  uint2* __restrict__ hi,
                                                  uint2* __restrict__ lo, int n4) {
    int i = blockIdx.x * 256 + threadIdx.x;
    if (i >= n4) return;
    float4 v = in[i];
    uint32_t h01, l01, h23, l23;
    split2(v.x, v.y, h01, l01);
    split2(v.z, v.w, h23, l23);
    hi[i] = make_uint2(h01, h23);
    lo[i] = make_uint2(l01, l23);
}

// ---------------------------------------------------------------------------
// HMMA bf16x3 GEMM: C = X @ W^T + bias (optionally *scale).
// MODE 0: fp32 out C[m*NE+n].  MODE 1: bf16 hi/lo scatter to [B,H,T,D].
// ---------------------------------------------------------------------------
#define PITCH_B 80
#define MAT_BYTES (128*PITCH_B)
#define STAGE_BYTES (4*MAT_BYTES)
#define NCHUNK (NE/32)

template<int MODE>
__global__ __launch_bounds__(256) void gemm_mma(
    const __nv_bfloat16* __restrict__ xhi, const __nv_bfloat16* __restrict__ xlo,
    const __nv_bfloat16* __restrict__ whi, const __nv_bfloat16* __restrict__ wlo,
    const float* __restrict__ bias, float* __restrict__ C,
    __nv_bfloat16* __restrict__ Chi, __nv_bfloat16* __restrict__ Clo, float scale)
{
    extern __shared__ __align__(256) char smem[];
    const uint32_t sb = smem_u32(smem);
    const int tid = threadIdx.x;
    const int wid = tid >> 5, lane = tid & 31;
    const int wm = wid >> 1, wn = wid & 1;
    const int n0 = blockIdx.x * 128, m0 = blockIdx.y * 128;

    const __nv_bfloat16* bases[4] = { xhi, xlo, whi, wlo };

    const int lr = lane & 15;
    const int kb8 = (lane >> 4) << 4;
    uint32_t aoff[2], boff[4];
    #pragma unroll
    for (int i = 0; i < 2; ++i)
        aoff[i] = (uint32_t)((wm*32 + i*16 + lr) * PITCH_B + kb8);
    #pragma unroll
    for (int j = 0; j < 4; ++j)
        boff[j] = (uint32_t)((wn*64 + j*16 + lr) * PITCH_B + kb8);

    float acc[2][8][4];
    #pragma unroll
    for (int i = 0; i < 2; ++i)
        #pragma unroll
        for (int j = 0; j < 8; ++j)
            #pragma unroll
            for (int r = 0; r < 4; ++r) acc[i][j][r] = 0.f;

    auto load_stage = [&](int stage, int kt) {
        const uint32_t sbase = sb + stage * STAGE_BYTES;
        #pragma unroll
        for (int t = 0; t < 4; ++t) {
            #pragma unroll
            for (int it = 0; it < 2; ++it) {
                int idx = tid + it * 256;
                int row = idx >> 2, c16 = idx & 3;
                int rg = ((t < 2) ? m0 : n0) + row;
                const __nv_bfloat16* src = bases[t] + (long)rg * NE + kt + c16 * 8;
                uint32_t dst = sbase + t * MAT_BYTES + row * PITCH_B + c16 * 16;
                CP_ASYNC16(dst, src);
            }
        }
        CP_COMMIT();
    };

    load_stage(0, 0);

    for (int c = 0; c < NCHUNK; ++c) {
        if (c + 1 < NCHUNK) {
            load_stage((c + 1) & 1, (c + 1) * 32);
            CP_WAIT(1);
        } else {
            CP_WAIT(0);
        }
        __syncthreads();

        const uint32_t sA_hi = sb + (c & 1) * STAGE_BYTES;
        const uint32_t sA_lo = sA_hi + MAT_BYTES;
        const uint32_t sB_hi = sA_hi + 2 * MAT_BYTES;
        const uint32_t sB_lo = sA_hi + 3 * MAT_BYTES;

        #pragma unroll
        for (int ks = 0; ks < 2; ++ks) {
            const uint32_t kbyte = ks * 32;
            uint32_t ah[2][4], al[2][4], bh[4][4], bl[4][4];
            #pragma unroll
            for (int i = 0; i < 2; ++i) {
                ldsm_x4(ah[i][0], ah[i][1], ah[i][2], ah[i][3], sA_hi + aoff[i] + kbyte);
                ldsm_x4(al[i][0], al[i][1], al[i][2], al[i][3], sA_lo + aoff[i] + kbyte);
            }
            #pragma unroll
            for (int j = 0; j < 4; ++j) {
                ldsm_x4(bh[j][0], bh[j][1], bh[j][2], bh[j][3], sB_hi + boff[j] + kbyte);
                ldsm_x4(bl[j][0], bl[j][1], bl[j][2], bl[j][3], sB_lo + boff[j] + kbyte);
            }
            #pragma unroll
            for (int i = 0; i < 2; ++i) {
                #pragma unroll
                for (int j = 0; j < 4; ++j) {
                    mma_bf16(acc[i][2*j],   ah[i], bh[j][0], bh[j][2]);
                    mma_bf16(acc[i][2*j+1], ah[i], bh[j][1], bh[j][3]);
                    mma_bf16(acc[i][2*j],   ah[i], bl[j][0], bl[j][2]);
                    mma_bf16(acc[i][2*j+1], ah[i], bl[j][1], bl[j][3]);
                    mma_bf16(acc[i][2*j],   al[i], bh[j][0], bh[j][2]);
                    mma_bf16(acc[i][2*j+1], al[i], bh[j][1], bh[j][3]);
                }
            }
        }
        __syncthreads();
    }

    const int qr = lane >> 2, qc = (lane & 3) * 2;
    #pragma unroll
    for (int i = 0; i < 2; ++i) {
        #pragma unroll
        for (int j = 0; j < 8; ++j) {
            const int n = n0 + wn*64 + j*8 + qc;
            const float b0 = bias[n], b1 = bias[n + 1];
            #pragma unroll
            for (int r8 = 0; r8 < 2; ++r8) {
                const int m = m0 + wm*32 + i*16 + qr + r8*8;
                float vx = acc[i][j][r8*2]     + b0;
                float vy = acc[i][j][r8*2 + 1] + b1;
                if (MODE == 0) {
                    *reinterpret_cast<float2*>(&C[(long)m * NE + n]) = make_float2(vx, vy);
                } else {
                    vx *= scale; vy *= scale;
                    uint32_t hp, lp;
                    split2(vx, vy, hp, lp);
                    const int b = m >> 11, t = m & 2047, h = n >> 6, d = n & 63;
                    const long off = ((((long)(b*NH + h) * NT) + t) << 6) + d;
                    *reinterpret_cast<uint32_t*>(&Chi[off]) = hp;
                    *reinterpret_cast<uint32_t*>(&Clo[off]) = lp;
                }
            }
        }
    }
}

// ---------------------------------------------------------------------------
// Tensor-core causal flash attention (bf16x3), all-bf16 operands.
// CTA: 128 q-rows x (head, batch). 8 warps, each 16 q-rows x full 64 kv-cols.
// Q/K/V already bf16 hi/lo in gmem (scale folded into Q by projection GEMM).
// cp.async double-buffered kv stages; V consumed via ldmatrix.trans.
// Output written pre-split (hi/lo) into the O-projection input buffers.
// ---------------------------------------------------------------------------
#define APITCH 144                     // 64 bf16 = 128B + 16B pad
#define QBYTES (128*APITCH)            // 18432 per Q matrix
#define KVMAT  (64*APITCH)             // 9216 per kv matrix
#define KVSTAGE (4*KVMAT)              // KH, KL, VH, VL = 36864
#define OFF_KV (2*QBYTES)              // 36864
#define ATTN_SMEM (OFF_KV + 2*KVSTAGE) // 110592

__global__ __launch_bounds__(256) void attn_mma()
{
    extern __shared__ __align__(256) char smem[];
    const uint32_t sb = smem_u32(smem);
    const int tid = threadIdx.x, wid = tid >> 5, lane = tid & 31;
    const int qt = blockIdx.x;
    const int h = blockIdx.y, b = blockIdx.z;

    const long hb = (long)(b*NH + h) * NT * ND;
    const __nv_bfloat16* srcsQ[2] = { g_qhi + hb + (long)qt*128*ND, g_qlo + hb + (long)qt*128*ND };
    const __nv_bfloat16* srcsKV[4] = { g_khi + hb, g_klo + hb, g_vhi + hb, g_vlo + hb };

    // ---- issue Q loads (8 cp per thread) + kv stage 0, one commit group ----
    #pragma unroll
    for (int t = 0; t < 2; ++t) {
        #pragma unroll
        for (int it = 0; it < 4; ++it) {
            int idx = tid + it * 256;           // 1024 = 128 rows x 8
            int row = idx >> 3, c16 = idx & 7;
            CP_ASYNC16(sb + t*QBYTES + row*APITCH + c16*16,
                       srcsQ[t] + (long)row*ND + c16*8);
        }
    }
    auto load_kv = [&](int stage, int kt) {
        const uint32_t sbase = sb + OFF_KV + stage * KVSTAGE;
        #pragma unroll
        for (int t = 0; t < 4; ++t) {
            #pragma unroll
            for (int it = 0; it < 2; ++it) {
                int idx = tid + it * 256;       // 512 = 64 rows x 8
                int row = idx >> 3, c16 = idx & 7;
                CP_ASYNC16(sbase + t*KVMAT + row*APITCH + c16*16,
                           srcsKV[t] + (long)(kt*64 + row)*ND + c16*8);
            }
        }
        CP_COMMIT();
    };
    load_kv(0, 0);   // commits Q + stage0 together

    const int lr = lane & 15;
    const int kb16 = (lane >> 4) << 4;
    const uint32_t aoffQ = (uint32_t)((wid*16 + lr) * APITCH + kb16);
    const uint32_t koff  = (uint32_t)(lr * APITCH + kb16);

    float m0 = -INFINITY, m1 = -INFINITY, l0 = 0.f, l1 = 0.f;
    float o[8][4];
    #pragma unroll
    for (int j = 0; j < 8; ++j)
        #pragma unroll
        for (int r = 0; r < 4; ++r) o[j][r] = 0.f;

    const int nkt = 2*qt + 2;
    const int rowg0 = qt*128 + wid*16 + (lane >> 2);
    const int qc2 = (lane & 3) * 2;

    for (int kt = 0; kt < nkt; ++kt) {
        if (kt + 1 < nkt) { load_kv((kt + 1) & 1, kt + 1); CP_WAIT(1); }
        else              { CP_WAIT(0); }
        __syncthreads();

        const uint32_t sK_hi = sb + OFF_KV + (kt & 1) * KVSTAGE;
        const uint32_t sK_lo = sK_hi + KVMAT;
        const uint32_t sV_hi = sK_hi + 2*KVMAT;
        const uint32_t sV_lo = sK_hi + 3*KVMAT;

        // ---- S = Q @ K^T (bf16x3) ----
        float s[8][4];
        #pragma unroll
        for (int j = 0; j < 8; ++j)
            #pragma unroll
            for (int r = 0; r < 4; ++r) s[j][r] = 0.f;

        #pragma unroll
        for (int ks = 0; ks < 4; ++ks) {
            const uint32_t kb = ks * 32;
            uint32_t ah[4], al[4];
            ldsm_x4(ah[0], ah[1], ah[2], ah[3], sb + aoffQ + kb);
            ldsm_x4(al[0], al[1], al[2], al[3], sb + QBYTES + aoffQ + kb);
            #pragma unroll
            for (int t = 0; t < 4; ++t) {
                uint32_t bh[4], bl[4];
                ldsm_x4(bh[0], bh[1], bh[2], bh[3], sK_hi + koff + t*16*APITCH + kb);
                ldsm_x4(bl[0], bl[1], bl[2], bl[3], sK_lo + koff + t*16*APITCH + kb);
                mma_bf16(s[2*t],   ah, bh[0], bh[2]);
                mma_bf16(s[2*t+1], ah, bh[1], bh[3]);
                mma_bf16(s[2*t],   ah, bl[0], bl[2]);
                mma_bf16(s[2*t+1], ah, bl[1], bl[3]);
                mma_bf16(s[2*t],   al, bh[0], bh[2]);
                mma_bf16(s[2*t+1], al, bh[1], bh[3]);
            }
        }

        // ---- causal mask (only diagonal-straddling tiles) ----
        if (kt >= 2*qt) {
            const int colbase = kt*64 + qc2;
            #pragma unroll
            for (int j = 0; j < 8; ++j) {
                int c0 = colbase + j*8, c1 = c0 + 1;
                if (c0 > rowg0)     s[j][0] = -1e30f;
                if (c1 > rowg0)     s[j][1] = -1e30f;
                if (c0 > rowg0 + 8) s[j][2] = -1e30f;
                if (c1 > rowg0 + 8) s[j][3] = -1e30f;
            }
        }

        // ---- streaming softmax ----
        float rm0 = -1e30f, rm1 = -1e30f;
        #pragma unroll
        for (int j = 0; j < 8; ++j) {
            rm0 = fmaxf(rm0, fmaxf(s[j][0], s[j][1]));
            rm1 = fmaxf(rm1, fmaxf(s[j][2], s[j][3]));
        }
        rm0 = fmaxf(rm0, __shfl_xor_sync(0xffffffffu, rm0, 1));
        rm0 = fmaxf(rm0, __shfl_xor_sync(0xffffffffu, rm0, 2));
        rm1 = fmaxf(rm1, __shfl_xor_sync(0xffffffffu, rm1, 1));
        rm1 = fmaxf(rm1, __shfl_xor_sync(0xffffffffu, rm1, 2));
        const float mn0 = fmaxf(m0, rm0), mn1 = fmaxf(m1, rm1);
        const float cr0 = __expf(m0 - mn0), cr1 = __expf(m1 - mn1);
        float sum0 = 0.f, sum1 = 0.f;
        #pragma unroll
        for (int j = 0; j < 8; ++j) {
            s[j][0] = __expf(s[j][0] - mn0);
            s[j][1] = __expf(s[j][1] - mn0);
            s[j][2] = __expf(s[j][2] - mn1);
            s[j][3] = __expf(s[j][3] - mn1);
            sum0 += s[j][0] + s[j][1];
            sum1 += s[j][2] + s[j][3];
        }
        sum0 += __shfl_xor_sync(0xffffffffu, sum0, 1);
        sum0 += __shfl_xor_sync(0xffffffffu, sum0, 2);
        sum1 += __shfl_xor_sync(0xffffffffu, sum1, 1);
        sum1 += __shfl_xor_sync(0xffffffffu, sum1, 2);
        l0 = l0*cr0 + sum0; l1 = l1*cr1 + sum1;
        m0 = mn0; m1 = mn1;
        #pragma unroll
        for (int j = 0; j < 8; ++j) {
            o[j][0] *= cr0; o[j][1] *= cr0;
            o[j][2] *= cr1; o[j][3] *= cr1;
        }

        // ---- O += P @ V (bf16x3, P split in-register, V via ldmatrix.trans) ----
        #pragma unroll
        for (int ks = 0; ks < 4; ++ks) {
            uint32_t ph[4], pl[4];
            {
                const float* r0 = s[2*ks];
                const float* r1 = s[2*ks+1];
                split2(r0[0], r0[1], ph[0], pl[0]);
                split2(r0[2], r0[3], ph[1], pl[1]);
                split2(r1[0], r1[1], ph[2], pl[2]);
                split2(r1[2], r1[3], ph[3], pl[3]);
            }
            const uint32_t vrow = (uint32_t)((ks*16 + lr) * APITCH + kb16);
            #pragma unroll
            for (int t = 0; t < 4; ++t) {
                uint32_t vh[4], vl[4];
                ldsm_x4_t(vh[0], vh[1], vh[2], vh[3], sV_hi + vrow + t*32);
                ldsm_x4_t(vl[0], vl[1], vl[2], vl[3], sV_lo + vrow + t*32);
                mma_bf16(o[2*t],   ph, vh[0], vh[1]);
                mma_bf16(o[2*t+1], ph, vh[2], vh[3]);
                mma_bf16(o[2*t],   ph, vl[0], vl[1]);
                mma_bf16(o[2*t+1], ph, vl[2], vl[3]);
                mma_bf16(o[2*t],   pl, vh[0], vh[1]);
                mma_bf16(o[2*t+1], pl, vh[2], vh[3]);
            }
        }
        __syncthreads();   // release kv stage before next iteration reloads it
    }

    // ---- finalize: O /= l, write pre-split into O-projection inputs ----
    const float il0 = 1.f / l0, il1 = 1.f / l1;
    const int t0 = qt*128 + wid*16 + (lane >> 2);
    const long rowbase = ((long)b*NT + t0) * NE + h*64;
    #pragma unroll
    for (int j = 0; j < 8; ++j) {
        const int d = j*8 + qc2;
        uint32_t hp, lp;
        split2(o[j][0]*il0, o[j][1]*il0, hp, lp);
        *reinterpret_cast<uint32_t*>(&g_xhi[rowbase + d]) = hp;
        *reinterpret_cast<uint32_t*>(&g_xlo[rowbase + d]) = lp;
        split2(o[j][2]*il1, o[j][3]*il1, hp, lp);
        *reinterpret_cast<uint32_t*>(&g_xhi[rowbase + 8*NE + d]) = hp;
        *reinterpret_cast<uint32_t*>(&g_xlo[rowbase + 8*NE + d]) = lp;
    }
}

// ---------------------------------------------------------------------------
extern "C" void kernel_launch(void* const* d_in, const int* in_sizes, int n_in,
                              void* d_out, int out_size)
{
    const float* query  = (const float*)d_in[0];
    const float* key_in = (const float*)d_in[1];
    const float* value  = (const float*)d_in[2];
    // d_in[3] = mask (exact tril -> causal predicate, not read)
    const float* Wq = (const float*)d_in[4];
    const float* bq = (const float*)d_in[5];
    const float* Wk = (const float*)d_in[6];
    const float* bk = (const float*)d_in[7];
    const float* Wv = (const float*)d_in[8];
    const float* bv = (const float*)d_in[9];
    const float* Wo = (const float*)d_in[10];
    const float* bo = (const float*)d_in[11];
    float* out = (float*)d_out;

    __nv_bfloat16 *qhi, *qlo, *khi, *klo, *vhi, *vlo, *xhi, *xlo, *whi, *wlo;
    cudaGetSymbolAddress((void**)&qhi, g_qhi);
    cudaGetSymbolAddress((void**)&qlo, g_qlo);
    cudaGetSymbolAddress((void**)&khi, g_khi);
    cudaGetSymbolAddress((void**)&klo, g_klo);
    cudaGetSymbolAddress((void**)&vhi, g_vhi);
    cudaGetSymbolAddress((void**)&vlo, g_vlo);
    cudaGetSymbolAddress((void**)&xhi, g_xhi);
    cudaGetSymbolAddress((void**)&xlo, g_xlo);
    cudaGetSymbolAddress((void**)&whi, g_whi);
    cudaGetSymbolAddress((void**)&wlo, g_wlo);

    const int gemm_smem = 2 * STAGE_BYTES;   // 81920
    cudaFuncSetAttribute(gemm_mma<0>, cudaFuncAttributeMaxDynamicSharedMemorySize, gemm_smem);
    cudaFuncSetAttribute(gemm_mma<1>, cudaFuncAttributeMaxDynamicSharedMemorySize, gemm_smem);
    cudaFuncSetAttribute(attn_mma, cudaFuncAttributeMaxDynamicSharedMemorySize, ATTN_SMEM);

    const int n4x = NM * NE / 4;
    const int n4w = NE * NE / 4;
    dim3 gridG(NE / 128, NM / 128);
    const float qscale = 0.125f;   // 1/sqrt(D)

    conv_split<<<n4x / 256, 256>>>((const float4*)query, (uint2*)xhi, (uint2*)xlo, n4x);
    conv_split<<<n4w / 256, 256>>>((const float4*)Wq, (uint2*)whi, (uint2*)wlo, n4w);
    gemm_mma<1><<<gridG, 256, gemm_smem>>>(xhi, xlo, whi, wlo, bq, nullptr, qhi, qlo, qscale);

    conv_split<<<n4x / 256, 256>>>((const float4*)key_in, (uint2*)xhi, (uint2*)xlo, n4x);
    conv_split<<<n4w / 256, 256>>>((const float4*)Wk, (uint2*)whi, (uint2*)wlo, n4w);
    gemm_mma<1><<<gridG, 256, gemm_smem>>>(xhi, xlo, whi, wlo, bk, nullptr, khi, klo, 1.f);

    conv_split<<<n4x / 256, 256>>>((const float4*)value, (uint2*)xhi, (uint2*)xlo, n4x);
    conv_split<<<n4w / 256, 256>>>((const float4*)Wv, (uint2*)whi, (uint2*)wlo, n4w);
    gemm_mma<1><<<gridG, 256, gemm_smem>>>(xhi, xlo, whi, wlo, bv, nullptr, vhi, vlo, 1.f);

    attn_mma<<<dim3(16, NH, NB), 256, ATTN_SMEM>>>();   // writes xhi/xlo

    conv_split<<<n4w / 256, 256>>>((const float4*)Wo, (uint2*)whi, (uint2*)wlo, n4w);
    gemm_mma<0><<<gridG, 256, gemm_smem>>>(xhi, xlo, whi, wlo, bo, out, nullptr, nullptr, 1.f);
}